// round 3
// baseline (speedup 1.0000x reference)
#include <cuda_runtime.h>

// Problem constants (from reference: B=4096, H=300 (=z_dim), T=64)
#define BQ 4096
#define HD 300
#define FH (4 * HD)
#define TT 64

// Ping-pong hidden states (read by all CTAs while being rewritten -> double buffer).
// Cell states are owner-exclusive -> in-place.
__device__ __align__(128) float g_h0[2][BQ * HD];
__device__ __align__(128) float g_c0[BQ * HD];
__device__ __align__(128) float g_h1[2][BQ * HD];
__device__ __align__(128) float g_c1[BQ * HD];

__global__ void zero_kernel(float* __restrict__ p, int n) {
    int i = blockIdx.x * blockDim.x + threadIdx.x;
    int stride = gridDim.x * blockDim.x;
    for (; i < n; i += stride) p[i] = 0.0f;
}

// One fused LSTM cell: gates = X @ Wih^T + Hin @ Whh^T + (bih+bhh); update c,h.
// Tiling: CTA = 128 batch rows x 32 hidden units (=128 gate columns), K = 600.
// Gate-column interleave: n -> unit j0 + (n>>2), gate (n&3). Each thread's 8
// accumulator columns = 2 units x 4 gates -> full cell update stays thread-local.
__global__ __launch_bounds__(256, 2)
void lstm_cell_kernel(const float* __restrict__ X,
                      const float* __restrict__ Hin,
                      float* __restrict__ C,
                      float* __restrict__ Hout,
                      const float* __restrict__ Wih,
                      const float* __restrict__ Whh,
                      const float* __restrict__ bih,
                      const float* __restrict__ bhh,
                      float* __restrict__ Y)  // == out + t*HD, or nullptr
{
    __shared__ float As[8][128];   // [k][m]
    __shared__ float Bs[8][128];   // [k][n]

    const int tid = threadIdx.x;
    const int tx = tid & 15;       // 0..15 -> 8 gate columns
    const int ty = tid >> 4;       // 0..15 -> 8 batch rows
    const int m0 = blockIdx.y * 128;
    const int j0 = blockIdx.x * 32;

    // Global-load assignment: each thread loads one float4 of A and of B per K-tile.
    const int lm = tid >> 1;           // 0..127
    const int lk = (tid & 1) * 4;      // 0 or 4

    // B (= W^T) column lm maps to W row: gate (lm&3), unit j0 + (lm>>2)
    const int bu = j0 + (lm >> 2);
    const int bg = lm & 3;
    const bool bvalid = (bu < HD);
    const long brow = (long)(bg * HD + bu) * HD;

    float acc[8][8];
#pragma unroll
    for (int i = 0; i < 8; ++i)
#pragma unroll
        for (int j = 0; j < 8; ++j) acc[i][j] = 0.0f;

    // Bias per thread-column (same across rows)
    float bias[8];
#pragma unroll
    for (int jj = 0; jj < 8; ++jj) {
        int n = tx * 8 + jj;
        int u = j0 + (n >> 2);
        int g = n & 3;
        bias[jj] = (u < HD) ? (bih[g * HD + u] + bhh[g * HD + u]) : 0.0f;
    }

#pragma unroll 1
    for (int part = 0; part < 2; ++part) {
        const float* Ag = part ? Hin : X;
        const float* Wg = part ? Whh : Wih;
#pragma unroll 1
        for (int k0 = 0; k0 < HD; k0 += 8) {
            // K = 300 is not a multiple of 8: last tile's upper half (k>=300) is zero.
            const bool kvalid = (k0 + lk) < HD;
            float4 a4 = make_float4(0.f, 0.f, 0.f, 0.f);
            float4 b4 = make_float4(0.f, 0.f, 0.f, 0.f);
            if (kvalid) {
                a4 = *(const float4*)(Ag + (long)(m0 + lm) * HD + k0 + lk);
                if (bvalid) b4 = *(const float4*)(Wg + brow + k0 + lk);
            }
            As[lk + 0][lm] = a4.x; As[lk + 1][lm] = a4.y;
            As[lk + 2][lm] = a4.z; As[lk + 3][lm] = a4.w;
            Bs[lk + 0][lm] = b4.x; Bs[lk + 1][lm] = b4.y;
            Bs[lk + 2][lm] = b4.z; Bs[lk + 3][lm] = b4.w;
            __syncthreads();

#pragma unroll
            for (int kk = 0; kk < 8; ++kk) {
                float ar[8], br[8];
                *(float4*)&ar[0] = *(const float4*)&As[kk][ty * 8 + 0];
                *(float4*)&ar[4] = *(const float4*)&As[kk][ty * 8 + 4];
                *(float4*)&br[0] = *(const float4*)&Bs[kk][tx * 8 + 0];
                *(float4*)&br[4] = *(const float4*)&Bs[kk][tx * 8 + 4];
#pragma unroll
                for (int i = 0; i < 8; ++i)
#pragma unroll
                    for (int j = 0; j < 8; ++j)
                        acc[i][j] = fmaf(ar[i], br[j], acc[i][j]);
            }
            __syncthreads();
        }
    }

    // Epilogue: per (row, unit) full LSTM update. PyTorch gate order i,f,g,o.
#pragma unroll
    for (int i = 0; i < 8; ++i) {
        const long b = m0 + ty * 8 + i;
#pragma unroll
        for (int uu = 0; uu < 2; ++uu) {
            const int u = j0 + tx * 2 + uu;
            if (u >= HD) continue;
            const float iv = acc[i][uu * 4 + 0] + bias[uu * 4 + 0];
            const float fv = acc[i][uu * 4 + 1] + bias[uu * 4 + 1];
            const float gv = acc[i][uu * 4 + 2] + bias[uu * 4 + 2];
            const float ov = acc[i][uu * 4 + 3] + bias[uu * 4 + 3];
            const float ig = 1.0f / (1.0f + __expf(-iv));
            const float fg = 1.0f / (1.0f + __expf(-fv));
            const float gg = tanhf(gv);
            const float og = 1.0f / (1.0f + __expf(-ov));
            const long idx = b * HD + u;
            const float cn = fg * C[idx] + ig * gg;
            const float hn = og * tanhf(cn);
            C[idx] = cn;
            Hout[idx] = hn;
            if (Y) Y[b * (long)(TT * HD) + u] = hn;
        }
    }
}

extern "C" void kernel_launch(void* const* d_in, const int* in_sizes, int n_in,
                              void* d_out, int out_size) {
    const float* z    = (const float*)d_in[0];
    const float* Wih0 = (const float*)d_in[1];
    const float* Whh0 = (const float*)d_in[2];
    const float* bih0 = (const float*)d_in[3];
    const float* bhh0 = (const float*)d_in[4];
    const float* Wih1 = (const float*)d_in[5];
    const float* Whh1 = (const float*)d_in[6];
    const float* bih1 = (const float*)d_in[7];
    const float* bhh1 = (const float*)d_in[8];
    float* out = (float*)d_out;

    float *h0, *c0, *h1, *c1;
    cudaGetSymbolAddress((void**)&h0, g_h0);
    cudaGetSymbolAddress((void**)&c0, g_c0);
    cudaGetSymbolAddress((void**)&h1, g_h1);
    cudaGetSymbolAddress((void**)&c1, g_c1);

    const int n = BQ * HD;
    zero_kernel<<<592, 256>>>(h0, n);       // h0[0]
    zero_kernel<<<592, 256>>>(h1, n);       // h1[0]
    zero_kernel<<<592, 256>>>(c0, n);
    zero_kernel<<<592, 256>>>(c1, n);

    // Grid: 10 unit-tiles (ceil(300/32)) x 32 batch-tiles
    dim3 grid(10, 32);
    for (int t = 0; t < TT; ++t) {
        const int p = t & 1;
        const float* x0 = t ? (h1 + p * n) : z;
        // Layer 0: reads h0[p], writes h0[p^1]; c0 in place.
        lstm_cell_kernel<<<grid, 256>>>(x0, h0 + p * n, c0, h0 + (p ^ 1) * n,
                                        Wih0, Whh0, bih0, bhh0, nullptr);
        // Layer 1: x = fresh h0; reads h1[p], writes h1[p^1]; c1 in place; emits out[:, t, :].
        lstm_cell_kernel<<<grid, 256>>>(h0 + (p ^ 1) * n, h1 + p * n, c1, h1 + (p ^ 1) * n,
                                        Wih1, Whh1, bih1, bhh1, out + (long)t * HD);
    }
}

// round 7
// speedup vs baseline: 3.3725x; 3.3725x over previous
#include <cuda_runtime.h>
#include <cuda_fp16.h>
#include <cstdint>

#define BQ 4096
#define HDIM 300
#define HP 320
#define KA 640
#define TT 64
#define NPAD 1280        // padded gate-cols (320 units x 4)
#define NCH 20           // K chunks of 32
#define STAGE 32768
#define SMEMB (3 * STAGE)

__device__ __align__(128) __half g_A0hi[2][(size_t)BQ * KA];
__device__ __align__(128) __half g_A0lo[2][(size_t)BQ * KA];
__device__ __align__(128) __half g_A1hi[2][(size_t)BQ * KA];
__device__ __align__(128) __half g_A1lo[2][(size_t)BQ * KA];
__device__ __align__(128) __half g_Bhi[2][(size_t)NPAD * KA];
__device__ __align__(128) __half g_Blo[2][(size_t)NPAD * KA];
__device__ __align__(128) float g_biasR[2][NPAD];
__device__ __align__(128) float g_c[2][(size_t)BQ * HDIM];

__device__ __forceinline__ uint32_t smem_u32(const void* p) {
    uint32_t a;
    asm("{ .reg .u64 t; cvta.to.shared.u64 t, %1; cvt.u32.u64 %0, t; }" : "=r"(a) : "l"(p));
    return a;
}
#define CP16(d, s) asm volatile("cp.async.cg.shared.global [%0], [%1], 16;" :: "r"((uint32_t)(d)), "l"(s) : "memory")
#define CP_COMMIT() asm volatile("cp.async.commit_group;" ::: "memory")
#define CP_WAIT(N) asm volatile("cp.async.wait_group " #N ";" ::: "memory")

// paired-row swizzle: rows are 32 halves (64B); two rows share a 128B SW128 atom row
__device__ __forceinline__ uint32_t swzoff(int row, int colh) {
    uint32_t o = ((uint32_t)(row >> 1) << 7) + ((uint32_t)(row & 1) << 6) + ((uint32_t)colh << 1);
    return o ^ ((o >> 3) & 0x70);
}
__device__ __forceinline__ void ldsm4(uint32_t* r, uint32_t a) {
    asm volatile("ldmatrix.sync.aligned.m8n8.x4.shared.b16 {%0,%1,%2,%3}, [%4];"
                 : "=r"(r[0]), "=r"(r[1]), "=r"(r[2]), "=r"(r[3]) : "r"(a));
}
__device__ __forceinline__ void mma16816(float* d, const uint32_t* a, const uint32_t* b) {
    asm volatile("mma.sync.aligned.m16n8k16.row.col.f32.f16.f16.f32 "
                 "{%0,%1,%2,%3}, {%4,%5,%6,%7}, {%8,%9}, {%0,%1,%2,%3};"
                 : "+f"(d[0]), "+f"(d[1]), "+f"(d[2]), "+f"(d[3])
                 : "r"(a[0]), "r"(a[1]), "r"(a[2]), "r"(a[3]), "r"(b[0]), "r"(b[1]));
}

// ---- FFMA-only transcendentals (keep MUFU off the critical path) ----
__device__ __forceinline__ float exp_fast(float x) {
    x = fminf(fmaxf(x, -87.0f), 87.0f);
    float r = x * 1.4426950408889634f;
    float nf = r + 12582912.0f;
    int ni = __float_as_int(nf) - 0x4B400000;
    nf -= 12582912.0f;
    float f = fmaf(nf, -0.6931471824645996f, x);
    f = fmaf(nf, 1.9046542e-9f, f);
    float p = 1.9875691500e-4f;
    p = fmaf(p, f, 1.3981999507e-3f);
    p = fmaf(p, f, 8.3334519073e-3f);
    p = fmaf(p, f, 4.1665795894e-2f);
    p = fmaf(p, f, 1.6666665459e-1f);
    p = fmaf(p, f, 5.0000001201e-1f);
    p = fmaf(p, f, 1.0f);
    p = fmaf(p, f, 1.0f);
    return p * __int_as_float((ni + 127) << 23);
}
__device__ __forceinline__ float rcp_fast(float d) {
    float y = __int_as_float(0x7EF311C3 - __float_as_int(d));
    y = fmaf(fmaf(-d, y, 1.0f), y, y);
    y = fmaf(fmaf(-d, y, 1.0f), y, y);
    y = fmaf(fmaf(-d, y, 1.0f), y, y);
    return y;
}
__device__ __forceinline__ float sigmoid_fast(float x) { return rcp_fast(1.0f + exp_fast(-x)); }
__device__ __forceinline__ float tanh_fast(float x) {
    return fmaf(-2.0f, rcp_fast(exp_fast(2.0f * x) + 1.0f), 1.0f);
}

// ---------------- fused LSTM cell ----------------
__global__ __launch_bounds__(256, 2)
void lstm_cell_mma(const __half* __restrict__ Ahi, const __half* __restrict__ Alo,
                   const __half* __restrict__ Bhi, const __half* __restrict__ Blo,
                   const float* __restrict__ biasR, float* __restrict__ C,
                   __half* __restrict__ d1hi, __half* __restrict__ d1lo,
                   __half* __restrict__ d2hi, __half* __restrict__ d2lo,
                   float* __restrict__ Y) {
    extern __shared__ __align__(1024) char smem[];
    const uint32_t sb = smem_u32(smem);
    const int tid = threadIdx.x, wid = tid >> 5, lane = tid & 31;
    const int mw = wid & 1, nw = wid >> 1;
    const int m0 = blockIdx.y * 128, nt = blockIdx.x;
    const int nbase = nt * 128;

    // per-thread ldmatrix address components
    const int a_r = mw * 64 + (lane & 7) + ((lane >> 3) & 1) * 8;
    const int a_c = ((lane >> 4) & 1) * 8;
    const int b_r = nw * 32 + (lane & 7) + ((lane >> 4) & 1) * 8;
    const int b_c = ((lane >> 3) & 1) * 8;

    float acc[4][4][4];
#pragma unroll
    for (int i = 0; i < 4; ++i)
#pragma unroll
        for (int j = 0; j < 4; ++j)
#pragma unroll
            for (int q = 0; q < 4; ++q) acc[i][j][q] = 0.0f;

    // stage loader: 4 tiles (Ahi|Alo|Bhi|Blo) of 128x32 halves each
    auto load_chunk = [&](int kc, uint32_t bs) {
        const int k0 = kc * 32;
#pragma unroll
        for (int j = 0; j < 8; ++j) {
            const int i = tid + j * 256;
            const int tile = i >> 9, g = i & 511;
            const int row = g >> 2, cb = g & 3;
            const uint32_t dst = bs + tile * 8192 + swzoff(row, cb * 8);
            const __half* src;
            if (tile == 0)      src = Ahi + (size_t)(m0 + row) * KA + k0 + cb * 8;
            else if (tile == 1) src = Alo + (size_t)(m0 + row) * KA + k0 + cb * 8;
            else if (tile == 2) src = Bhi + (size_t)(nbase + row) * KA + k0 + cb * 8;
            else                src = Blo + (size_t)(nbase + row) * KA + k0 + cb * 8;
            CP16(dst, src);
        }
        CP_COMMIT();
    };

    load_chunk(0, sb);
    load_chunk(1, sb + STAGE);

#pragma unroll 1
    for (int c = 0; c < NCH; ++c) {
        if (c + 1 < NCH) { CP_WAIT(1); } else { CP_WAIT(0); }
        __syncthreads();
        if (c + 2 < NCH) load_chunk(c + 2, sb + ((c + 2) % 3) * STAGE);

        const uint32_t bs = sb + (c % 3) * STAGE;
        const uint32_t tAhi = bs, tAlo = bs + 8192, tBhi = bs + 16384, tBlo = bs + 24576;
#pragma unroll
        for (int ks = 0; ks < 2; ++ks) {
            uint32_t Ah[4][4], Bh[2][4];
#pragma unroll
            for (int mi = 0; mi < 4; ++mi) ldsm4(Ah[mi], tAhi + swzoff(a_r + mi * 16, a_c + ks * 16));
#pragma unroll
            for (int nb = 0; nb < 2; ++nb) ldsm4(Bh[nb], tBhi + swzoff(b_r + nb * 16, b_c + ks * 16));
#pragma unroll
            for (int mi = 0; mi < 4; ++mi)
#pragma unroll
                for (int ni = 0; ni < 4; ++ni)
                    mma16816(acc[mi][ni], Ah[mi], &Bh[ni >> 1][(ni & 1) * 2]);
            uint32_t Al[4][4];
#pragma unroll
            for (int mi = 0; mi < 4; ++mi) ldsm4(Al[mi], tAlo + swzoff(a_r + mi * 16, a_c + ks * 16));
#pragma unroll
            for (int mi = 0; mi < 4; ++mi)
#pragma unroll
                for (int ni = 0; ni < 4; ++ni)
                    mma16816(acc[mi][ni], Al[mi], &Bh[ni >> 1][(ni & 1) * 2]);
            uint32_t Bl[2][4];
#pragma unroll
            for (int nb = 0; nb < 2; ++nb) ldsm4(Bl[nb], tBlo + swzoff(b_r + nb * 16, b_c + ks * 16));
#pragma unroll
            for (int mi = 0; mi < 4; ++mi)
#pragma unroll
                for (int ni = 0; ni < 4; ++ni)
                    mma16816(acc[mi][ni], Ah[mi], &Bl[ni >> 1][(ni & 1) * 2]);
        }
    }

    // ---- epilogue: shfl gate-exchange, full LSTM update, split-fp16 h writeback ----
    const int odd = lane & 1;
#pragma unroll
    for (int mi = 0; mi < 4; ++mi) {
#pragma unroll
        for (int ni = 0; ni < 4; ++ni) {
            float d0 = acc[mi][ni][0], d1 = acc[mi][ni][1], d2 = acc[mi][ni][2], d3 = acc[mi][ni][3];
            const float e0 = __shfl_xor_sync(0xFFFFFFFFu, d0, 1);
            const float e1 = __shfl_xor_sync(0xFFFFFFFFu, d1, 1);
            const float e2 = __shfl_xor_sync(0xFFFFFFFFu, d2, 1);
            const float e3 = __shfl_xor_sync(0xFFFFFFFFu, d3, 1);
            float iv, fv, gv, ov;
            int rl;
            if (!odd) { iv = d0; fv = d1; gv = e0; ov = e1; rl = lane >> 2; }
            else      { iv = e2; fv = e3; gv = d2; ov = d3; rl = (lane >> 2) + 8; }
            const int u = nt * 32 + nw * 8 + ni * 2 + ((lane >> 1) & 1);
            if (u < HDIM) {
                const int m = m0 + mw * 64 + mi * 16 + rl;
                const float4 bb = *(const float4*)(biasR + 4 * u);
                iv += bb.x; fv += bb.y; gv += bb.z; ov += bb.w;
                const float ig = sigmoid_fast(iv);
                const float fg = sigmoid_fast(fv);
                const float gg = tanh_fast(gv);
                const float og = sigmoid_fast(ov);
                const size_t ci = (size_t)m * HDIM + u;
                const float cn = fmaf(fg, C[ci], ig * gg);
                C[ci] = cn;
                const float h = og * tanh_fast(cn);
                const __half hh = __float2half_rn(h);
                const __half hl = __float2half_rn(h - __half2float(hh));
                const size_t ai = (size_t)m * KA + u;
                d1hi[ai] = hh; d1lo[ai] = hl;
                d2hi[ai] = hh; d2lo[ai] = hl;
                if (Y) Y[(size_t)m * (TT * HDIM) + u] = h;
            }
        }
    }
}

// ---------------- prep kernels ----------------
__global__ void prep_weights(const float* __restrict__ Wih0, const float* __restrict__ Whh0,
                             const float* __restrict__ Wih1, const float* __restrict__ Whh1) {
    const int total = 2 * NPAD * KA;
    for (int idx = blockIdx.x * blockDim.x + threadIdx.x; idx < total; idx += gridDim.x * blockDim.x) {
        const int l = idx / (NPAD * KA), r2 = idx % (NPAD * KA);
        const int n = r2 / KA, k = r2 % KA;
        const int unit = n >> 2, gate = n & 3;
        const int kp = k / HP, kk = k % HP;
        float w = 0.f;
        if (unit < HDIM && kk < HDIM) {
            const float* W = l ? (kp ? Whh1 : Wih1) : (kp ? Whh0 : Wih0);
            w = W[(size_t)(gate * HDIM + unit) * HDIM + kk];
        }
        const __half hi = __float2half_rn(w);
        g_Bhi[l][(size_t)n * KA + k] = hi;
        g_Blo[l][(size_t)n * KA + k] = __float2half_rn(w - __half2float(hi));
    }
}

__global__ void prep_bias(const float* __restrict__ bih0, const float* __restrict__ bhh0,
                          const float* __restrict__ bih1, const float* __restrict__ bhh1) {
    for (int idx = blockIdx.x * blockDim.x + threadIdx.x; idx < 2 * NPAD; idx += gridDim.x * blockDim.x) {
        const int l = idx / NPAD, n = idx % NPAD;
        const int unit = n >> 2, gate = n & 3;
        float v = 0.f;
        if (unit < HDIM)
            v = l ? (bih1[gate * HDIM + unit] + bhh1[gate * HDIM + unit])
                  : (bih0[gate * HDIM + unit] + bhh0[gate * HDIM + unit]);
        g_biasR[l][n] = v;
    }
}

__global__ void init_state(const float* __restrict__ z) {
    const __half zh = __float2half_rn(0.f);
    const size_t total = (size_t)BQ * KA;
    for (size_t idx = blockIdx.x * (size_t)blockDim.x + threadIdx.x; idx < total;
         idx += gridDim.x * (size_t)blockDim.x) {
        const int row = (int)(idx / KA), col = (int)(idx % KA);
        float v = (col < HDIM) ? z[(size_t)row * HDIM + col] : 0.f;
        const __half hi = __float2half_rn(v);
        g_A0hi[0][idx] = hi;
        g_A0lo[0][idx] = __float2half_rn(v - __half2float(hi));
        g_A0hi[1][idx] = zh; g_A0lo[1][idx] = zh;
        g_A1hi[0][idx] = zh; g_A1lo[0][idx] = zh;
        g_A1hi[1][idx] = zh; g_A1lo[1][idx] = zh;
        if (col < HDIM) {
            g_c[0][(size_t)row * HDIM + col] = 0.f;
            g_c[1][(size_t)row * HDIM + col] = 0.f;
        }
    }
}

// ---------------- host ----------------
extern "C" void kernel_launch(void* const* d_in, const int* in_sizes, int n_in,
                              void* d_out, int out_size) {
    const float* z    = (const float*)d_in[0];
    const float* Wih0 = (const float*)d_in[1];
    const float* Whh0 = (const float*)d_in[2];
    const float* bih0 = (const float*)d_in[3];
    const float* bhh0 = (const float*)d_in[4];
    const float* Wih1 = (const float*)d_in[5];
    const float* Whh1 = (const float*)d_in[6];
    const float* bih1 = (const float*)d_in[7];
    const float* bhh1 = (const float*)d_in[8];
    float* out = (float*)d_out;

    __half *A0hi, *A0lo, *A1hi, *A1lo, *Bhi, *Blo;
    float *biasR, *cst;
    cudaGetSymbolAddress((void**)&A0hi, g_A0hi);
    cudaGetSymbolAddress((void**)&A0lo, g_A0lo);
    cudaGetSymbolAddress((void**)&A1hi, g_A1hi);
    cudaGetSymbolAddress((void**)&A1lo, g_A1lo);
    cudaGetSymbolAddress((void**)&Bhi, g_Bhi);
    cudaGetSymbolAddress((void**)&Blo, g_Blo);
    cudaGetSymbolAddress((void**)&biasR, g_biasR);
    cudaGetSymbolAddress((void**)&cst, g_c);

    cudaFuncSetAttribute(lstm_cell_mma, cudaFuncAttributeMaxDynamicSharedMemorySize, SMEMB);

    prep_weights<<<2048, 256>>>(Wih0, Whh0, Wih1, Whh1);
    prep_bias<<<10, 256>>>(bih0, bhh0, bih1, bhh1);
    init_state<<<2048, 256>>>(z);

    const size_t AN = (size_t)BQ * KA;
    const size_t BN = (size_t)NPAD * KA;
    const size_t CN = (size_t)BQ * HDIM;
    dim3 grid(10, 32);
    for (int t = 0; t < TT; ++t) {
        const int p = t & 1, q = p ^ 1;
        // layer 0: reads A0[p]; h0_t -> A1[q] x-part, A0[q] h-part
        lstm_cell_mma<<<grid, 256, SMEMB>>>(
            A0hi + p * AN, A0lo + p * AN, Bhi, Blo, biasR, cst,
            A1hi + q * AN, A1lo + q * AN, A0hi + q * AN + HP, A0lo + q * AN + HP, nullptr);
        // layer 1: reads A1[q]; h1_t -> A0[q] x-part (feedback), A1[p] h-part; emits Y
        lstm_cell_mma<<<grid, 256, SMEMB>>>(
            A1hi + q * AN, A1lo + q * AN, Bhi + BN, Blo + BN, biasR + NPAD, cst + CN,
            A0hi + q * AN, A0lo + q * AN, A1hi + p * AN + HP, A1lo + p * AN + HP,
            out + (size_t)t * HDIM);
    }
}

// round 8
// speedup vs baseline: 3.9965x; 1.1850x over previous
#include <cuda_runtime.h>
#include <cuda_fp16.h>
#include <cstdint>

#define BQ 4096
#define HDIM 300
#define HP 304           // padded half-K (300 -> 304); h-part at [304, 608)
#define KA 608
#define TT 64
#define NPAD 1280        // padded gate-cols (320 units x 4)
#define NCH 19           // K chunks of 32
#define STAGE 24576      // Ahi 8K | Alo 8K | Bhi 4K | Blo 4K
#define SMEMB (3 * STAGE)

__device__ __align__(128) __half g_A0hi[2][(size_t)BQ * KA];
__device__ __align__(128) __half g_A0lo[2][(size_t)BQ * KA];
__device__ __align__(128) __half g_A1hi[2][(size_t)BQ * KA];
__device__ __align__(128) __half g_A1lo[2][(size_t)BQ * KA];
__device__ __align__(128) __half g_Bhi[2][(size_t)NPAD * KA];
__device__ __align__(128) __half g_Blo[2][(size_t)NPAD * KA];
__device__ __align__(128) float g_biasR[2][NPAD];
__device__ __align__(128) float g_c[2][(size_t)BQ * HDIM];

__device__ __forceinline__ uint32_t smem_u32(const void* p) {
    uint32_t a;
    asm("{ .reg .u64 t; cvta.to.shared.u64 t, %1; cvt.u32.u64 %0, t; }" : "=r"(a) : "l"(p));
    return a;
}
#define CP16(d, s) asm volatile("cp.async.cg.shared.global [%0], [%1], 16;" :: "r"((uint32_t)(d)), "l"(s) : "memory")
#define CP_COMMIT() asm volatile("cp.async.commit_group;" ::: "memory")
#define CP_WAIT(N) asm volatile("cp.async.wait_group " #N ";" ::: "memory")

// paired-row swizzle: rows are 32 halves (64B); two rows share a 128B SW128 atom row
__device__ __forceinline__ uint32_t swzoff(int row, int colh) {
    uint32_t o = ((uint32_t)(row >> 1) << 7) + ((uint32_t)(row & 1) << 6) + ((uint32_t)colh << 1);
    return o ^ ((o >> 3) & 0x70);
}
__device__ __forceinline__ void ldsm4(uint32_t* r, uint32_t a) {
    asm volatile("ldmatrix.sync.aligned.m8n8.x4.shared.b16 {%0,%1,%2,%3}, [%4];"
                 : "=r"(r[0]), "=r"(r[1]), "=r"(r[2]), "=r"(r[3]) : "r"(a));
}
__device__ __forceinline__ void mma16816(float* d, const uint32_t* a, const uint32_t* b) {
    asm volatile("mma.sync.aligned.m16n8k16.row.col.f32.f16.f16.f32 "
                 "{%0,%1,%2,%3}, {%4,%5,%6,%7}, {%8,%9}, {%0,%1,%2,%3};"
                 : "+f"(d[0]), "+f"(d[1]), "+f"(d[2]), "+f"(d[3])
                 : "r"(a[0]), "r"(a[1]), "r"(a[2]), "r"(a[3]), "r"(b[0]), "r"(b[1]));
}

// ---- FFMA-only transcendentals ----
__device__ __forceinline__ float exp_fast(float x) {
    x = fminf(fmaxf(x, -87.0f), 87.0f);
    float r = x * 1.4426950408889634f;
    float nf = r + 12582912.0f;
    int ni = __float_as_int(nf) - 0x4B400000;
    nf -= 12582912.0f;
    float f = fmaf(nf, -0.6931471824645996f, x);
    f = fmaf(nf, 1.9046542e-9f, f);
    float p = 1.9875691500e-4f;
    p = fmaf(p, f, 1.3981999507e-3f);
    p = fmaf(p, f, 8.3334519073e-3f);
    p = fmaf(p, f, 4.1665795894e-2f);
    p = fmaf(p, f, 1.6666665459e-1f);
    p = fmaf(p, f, 5.0000001201e-1f);
    p = fmaf(p, f, 1.0f);
    p = fmaf(p, f, 1.0f);
    return p * __int_as_float((ni + 127) << 23);
}
__device__ __forceinline__ float rcp_fast(float d) {
    float y = __int_as_float(0x7EF311C3 - __float_as_int(d));
    y = fmaf(fmaf(-d, y, 1.0f), y, y);
    y = fmaf(fmaf(-d, y, 1.0f), y, y);
    y = fmaf(fmaf(-d, y, 1.0f), y, y);
    return y;
}
__device__ __forceinline__ float sigmoid_fast(float x) { return rcp_fast(1.0f + exp_fast(-x)); }
__device__ __forceinline__ float tanh_fast(float x) {
    return fmaf(-2.0f, rcp_fast(exp_fast(2.0f * x) + 1.0f), 1.0f);
}

// ---------------- fused LSTM cell: CTA tile 128(M) x 64(N gate-cols) ----------------
__global__ __launch_bounds__(256, 3)
void lstm_cell_mma(const __half* __restrict__ Ahi, const __half* __restrict__ Alo,
                   const __half* __restrict__ Bhi, const __half* __restrict__ Blo,
                   const float* __restrict__ biasR, float* __restrict__ C,
                   __half* __restrict__ d1hi, __half* __restrict__ d1lo,
                   __half* __restrict__ d2hi, __half* __restrict__ d2lo,
                   float* __restrict__ Y) {
    extern __shared__ __align__(1024) char smem[];
    const uint32_t sb = smem_u32(smem);
    const int tid = threadIdx.x, wid = tid >> 5, lane = tid & 31;
    const int mw = wid & 3;        // 4 M-warps x 32 rows
    const int nw = wid >> 2;       // 2 N-warps x 32 cols
    const int m0 = blockIdx.y * 128, nt = blockIdx.x;
    const int nbase = nt * 64;

    // ldmatrix per-thread address components (same fragment mapping as r7 kernel)
    const int a_r = mw * 32 + (lane & 7) + ((lane >> 3) & 1) * 8;
    const int a_c = ((lane >> 4) & 1) * 8;
    const int b_r = nw * 32 + (lane & 7) + ((lane >> 4) & 1) * 8;
    const int b_c = ((lane >> 3) & 1) * 8;

    float acc[2][4][4];
#pragma unroll
    for (int i = 0; i < 2; ++i)
#pragma unroll
        for (int j = 0; j < 4; ++j)
#pragma unroll
            for (int q = 0; q < 4; ++q) acc[i][j][q] = 0.0f;

    // stage loader: Ahi(128x32) | Alo | Bhi(64x32) | Blo ; 1536 16B-granules, 6/thread
    auto load_chunk = [&](int kc, uint32_t bs) {
        const int k0 = kc * 32;
#pragma unroll
        for (int j = 0; j < 6; ++j) {
            const int i = tid + j * 256;
            if (i < 1024) {
                const int g = i & 511, row = g >> 2, cb = g & 3;
                const uint32_t dst = bs + (i >> 9) * 8192 + swzoff(row, cb * 8);
                const __half* src = ((i >> 9) ? Alo : Ahi) + (size_t)(m0 + row) * KA + k0 + cb * 8;
                CP16(dst, src);
            } else {
                const int g = i & 255, row = g >> 2, cb = g & 3;
                const uint32_t dst = bs + 16384 + ((i >> 8) & 1) * 4096 + swzoff(row, cb * 8);
                const __half* src = (((i >> 8) & 1) ? Blo : Bhi) + (size_t)(nbase + row) * KA + k0 + cb * 8;
                CP16(dst, src);
            }
        }
        CP_COMMIT();
    };

    load_chunk(0, sb);
    load_chunk(1, sb + STAGE);

#pragma unroll 1
    for (int c = 0; c < NCH; ++c) {
        if (c + 1 < NCH) { CP_WAIT(1); } else { CP_WAIT(0); }
        __syncthreads();
        if (c + 2 < NCH) load_chunk(c + 2, sb + ((c + 2) % 3) * STAGE);

        const uint32_t bs = sb + (c % 3) * STAGE;
        const uint32_t tAhi = bs, tAlo = bs + 8192, tBhi = bs + 16384, tBlo = bs + 20480;
#pragma unroll
        for (int ks = 0; ks < 2; ++ks) {
            uint32_t Ah[2][4], Bh[2][4];
#pragma unroll
            for (int mi = 0; mi < 2; ++mi) ldsm4(Ah[mi], tAhi + swzoff(a_r + mi * 16, a_c + ks * 16));
#pragma unroll
            for (int nb = 0; nb < 2; ++nb) ldsm4(Bh[nb], tBhi + swzoff(b_r + nb * 16, b_c + ks * 16));
#pragma unroll
            for (int mi = 0; mi < 2; ++mi)
#pragma unroll
                for (int ni = 0; ni < 4; ++ni)
                    mma16816(acc[mi][ni], Ah[mi], &Bh[ni >> 1][(ni & 1) * 2]);
            uint32_t Al[2][4];
#pragma unroll
            for (int mi = 0; mi < 2; ++mi) ldsm4(Al[mi], tAlo + swzoff(a_r + mi * 16, a_c + ks * 16));
#pragma unroll
            for (int mi = 0; mi < 2; ++mi)
#pragma unroll
                for (int ni = 0; ni < 4; ++ni)
                    mma16816(acc[mi][ni], Al[mi], &Bh[ni >> 1][(ni & 1) * 2]);
            uint32_t Bl[2][4];
#pragma unroll
            for (int nb = 0; nb < 2; ++nb) ldsm4(Bl[nb], tBlo + swzoff(b_r + nb * 16, b_c + ks * 16));
#pragma unroll
            for (int mi = 0; mi < 2; ++mi)
#pragma unroll
                for (int ni = 0; ni < 4; ++ni)
                    mma16816(acc[mi][ni], Ah[mi], &Bl[ni >> 1][(ni & 1) * 2]);
        }
    }

    // ---- epilogue: shfl gate-exchange, full LSTM update, split-fp16 h writeback ----
    const int odd = lane & 1;
#pragma unroll
    for (int mi = 0; mi < 2; ++mi) {
#pragma unroll
        for (int ni = 0; ni < 4; ++ni) {
            float d0 = acc[mi][ni][0], d1 = acc[mi][ni][1], d2 = acc[mi][ni][2], d3 = acc[mi][ni][3];
            const float e0 = __shfl_xor_sync(0xFFFFFFFFu, d0, 1);
            const float e1 = __shfl_xor_sync(0xFFFFFFFFu, d1, 1);
            const float e2 = __shfl_xor_sync(0xFFFFFFFFu, d2, 1);
            const float e3 = __shfl_xor_sync(0xFFFFFFFFu, d3, 1);
            float iv, fv, gv, ov;
            int rl;
            if (!odd) { iv = d0; fv = d1; gv = e0; ov = e1; rl = lane >> 2; }
            else      { iv = e2; fv = e3; gv = d2; ov = d3; rl = (lane >> 2) + 8; }
            const int u = nt * 16 + nw * 8 + ni * 2 + ((lane >> 1) & 1);
            if (u < HDIM) {
                const int m = m0 + mw * 32 + mi * 16 + rl;
                const float4 bb = *(const float4*)(biasR + 4 * u);
                iv += bb.x; fv += bb.y; gv += bb.z; ov += bb.w;
                const float ig = sigmoid_fast(iv);
                const float fg = sigmoid_fast(fv);
                const float gg = tanh_fast(gv);
                const float og = sigmoid_fast(ov);
                const size_t ci = (size_t)m * HDIM + u;
                const float cn = fmaf(fg, C[ci], ig * gg);
                C[ci] = cn;
                const float h = og * tanh_fast(cn);
                const __half hh = __float2half_rn(h);
                const __half hl = __float2half_rn(h - __half2float(hh));
                const size_t ai = (size_t)m * KA + u;
                d1hi[ai] = hh; d1lo[ai] = hl;
                d2hi[ai] = hh; d2lo[ai] = hl;
                if (Y) Y[(size_t)m * (TT * HDIM) + u] = h;
            }
        }
    }
}

// ---------------- prep kernels ----------------
__global__ void prep_weights(const float* __restrict__ Wih0, const float* __restrict__ Whh0,
                             const float* __restrict__ Wih1, const float* __restrict__ Whh1) {
    const int total = 2 * NPAD * KA;
    for (int idx = blockIdx.x * blockDim.x + threadIdx.x; idx < total; idx += gridDim.x * blockDim.x) {
        const int l = idx / (NPAD * KA), r2 = idx % (NPAD * KA);
        const int n = r2 / KA, k = r2 % KA;
        const int unit = n >> 2, gate = n & 3;
        const int kp = k / HP, kk = k % HP;
        float w = 0.f;
        if (unit < HDIM && kk < HDIM) {
            const float* W = l ? (kp ? Whh1 : Wih1) : (kp ? Whh0 : Wih0);
            w = W[(size_t)(gate * HDIM + unit) * HDIM + kk];
        }
        const __half hi = __float2half_rn(w);
        g_Bhi[l][(size_t)n * KA + k] = hi;
        g_Blo[l][(size_t)n * KA + k] = __float2half_rn(w - __half2float(hi));
    }
}

__global__ void prep_bias(const float* __restrict__ bih0, const float* __restrict__ bhh0,
                          const float* __restrict__ bih1, const float* __restrict__ bhh1) {
    for (int idx = blockIdx.x * blockDim.x + threadIdx.x; idx < 2 * NPAD; idx += gridDim.x * blockDim.x) {
        const int l = idx / NPAD, n = idx % NPAD;
        const int unit = n >> 2, gate = n & 3;
        float v = 0.f;
        if (unit < HDIM)
            v = l ? (bih1[gate * HDIM + unit] + bhh1[gate * HDIM + unit])
                  : (bih0[gate * HDIM + unit] + bhh0[gate * HDIM + unit]);
        g_biasR[l][n] = v;
    }
}

__global__ void init_state(const float* __restrict__ z) {
    const __half zh = __float2half_rn(0.f);
    const size_t total = (size_t)BQ * KA;
    for (size_t idx = blockIdx.x * (size_t)blockDim.x + threadIdx.x; idx < total;
         idx += gridDim.x * (size_t)blockDim.x) {
        const int row = (int)(idx / KA), col = (int)(idx % KA);
        float v = (col < HDIM) ? z[(size_t)row * HDIM + col] : 0.f;
        const __half hi = __float2half_rn(v);
        g_A0hi[0][idx] = hi;
        g_A0lo[0][idx] = __float2half_rn(v - __half2float(hi));
        g_A0hi[1][idx] = zh; g_A0lo[1][idx] = zh;
        g_A1hi[0][idx] = zh; g_A1lo[0][idx] = zh;
        g_A1hi[1][idx] = zh; g_A1lo[1][idx] = zh;
        if (col < HDIM) {
            g_c[0][(size_t)row * HDIM + col] = 0.f;
            g_c[1][(size_t)row * HDIM + col] = 0.f;
        }
    }
}

// ---------------- host ----------------
extern "C" void kernel_launch(void* const* d_in, const int* in_sizes, int n_in,
                              void* d_out, int out_size) {
    const float* z    = (const float*)d_in[0];
    const float* Wih0 = (const float*)d_in[1];
    const float* Whh0 = (const float*)d_in[2];
    const float* bih0 = (const float*)d_in[3];
    const float* bhh0 = (const float*)d_in[4];
    const float* Wih1 = (const float*)d_in[5];
    const float* Whh1 = (const float*)d_in[6];
    const float* bih1 = (const float*)d_in[7];
    const float* bhh1 = (const float*)d_in[8];
    float* out = (float*)d_out;

    __half *A0hi, *A0lo, *A1hi, *A1lo, *Bhi, *Blo;
    float *biasR, *cst;
    cudaGetSymbolAddress((void**)&A0hi, g_A0hi);
    cudaGetSymbolAddress((void**)&A0lo, g_A0lo);
    cudaGetSymbolAddress((void**)&A1hi, g_A1hi);
    cudaGetSymbolAddress((void**)&A1lo, g_A1lo);
    cudaGetSymbolAddress((void**)&Bhi, g_Bhi);
    cudaGetSymbolAddress((void**)&Blo, g_Blo);
    cudaGetSymbolAddress((void**)&biasR, g_biasR);
    cudaGetSymbolAddress((void**)&cst, g_c);

    cudaFuncSetAttribute(lstm_cell_mma, cudaFuncAttributeMaxDynamicSharedMemorySize, SMEMB);

    prep_weights<<<2048, 256>>>(Wih0, Whh0, Wih1, Whh1);
    prep_bias<<<10, 256>>>(bih0, bhh0, bih1, bhh1);
    init_state<<<2048, 256>>>(z);

    const size_t AN = (size_t)BQ * KA;
    const size_t BN = (size_t)NPAD * KA;
    const size_t CN = (size_t)BQ * HDIM;
    dim3 grid(20, 32);   // 20 N-tiles(64 cols) x 32 M-tiles(128 rows) = 640 CTAs
    for (int t = 0; t < TT; ++t) {
        const int p = t & 1, q = p ^ 1;
        // layer 0: reads A0[p]; h0_t -> A1[q] x-part, A0[q] h-part
        lstm_cell_mma<<<grid, 256, SMEMB>>>(
            A0hi + p * AN, A0lo + p * AN, Bhi, Blo, biasR, cst,
            A1hi + q * AN, A1lo + q * AN, A0hi + q * AN + HP, A0lo + q * AN + HP, nullptr);
        // layer 1: reads A1[q]; h1_t -> A0[q] x-part (feedback), A1[p] h-part; emits Y
        lstm_cell_mma<<<grid, 256, SMEMB>>>(
            A1hi + q * AN, A1lo + q * AN, Bhi + BN, Blo + BN, biasR + NPAD, cst + CN,
            A0hi + q * AN, A0lo + q * AN, A1hi + p * AN + HP, A1lo + p * AN + HP,
            out + (size_t)t * HDIM);
    }
}

// round 9
// speedup vs baseline: 5.3207x; 1.3314x over previous
#include <cuda_runtime.h>
#include <cuda_fp16.h>
#include <cstdint>

#define BQ 4096
#define HDIM 300
#define SEC 304          // per-section K (x-part or h-part), 38 granules of 8
#define KA 608           // total K
#define TT 64
#define NPAD 1216        // padded gate-cols (304 units x 4)
#define NCH 19           // K chunks of 32
#define STAGE 16384      // Ahi 4K | Alo 4K | Bhi 4K | Blo 4K
#define SMEMB (3 * STAGE)

// h states sectioned: [2 parity][4096 x 304] per hi/lo per layer; z static section
__device__ __align__(128) __half g_Zhi[(size_t)BQ * SEC];
__device__ __align__(128) __half g_Zlo[(size_t)BQ * SEC];
__device__ __align__(128) __half g_H0hi[2][(size_t)BQ * SEC];
__device__ __align__(128) __half g_H0lo[2][(size_t)BQ * SEC];
__device__ __align__(128) __half g_H1hi[2][(size_t)BQ * SEC];
__device__ __align__(128) __half g_H1lo[2][(size_t)BQ * SEC];
__device__ __align__(128) __half g_Bhi[2][(size_t)NPAD * KA];
__device__ __align__(128) __half g_Blo[2][(size_t)NPAD * KA];
__device__ __align__(128) float g_biasR[2][NPAD];
__device__ __align__(128) float g_c[2][(size_t)BQ * HDIM];

__device__ __forceinline__ uint32_t smem_u32(const void* p) {
    uint32_t a;
    asm("{ .reg .u64 t; cvta.to.shared.u64 t, %1; cvt.u32.u64 %0, t; }" : "=r"(a) : "l"(p));
    return a;
}
#define CP16(d, s) asm volatile("cp.async.cg.shared.global [%0], [%1], 16;" :: "r"((uint32_t)(d)), "l"(s) : "memory")
#define CP_COMMIT() asm volatile("cp.async.commit_group;" ::: "memory")
#define CP_WAIT(N) asm volatile("cp.async.wait_group " #N ";" ::: "memory")

// paired-row swizzle: rows are 32 halves (64B); two rows share a 128B atom row
__device__ __forceinline__ uint32_t swzoff(int row, int colh) {
    uint32_t o = ((uint32_t)(row >> 1) << 7) + ((uint32_t)(row & 1) << 6) + ((uint32_t)colh << 1);
    return o ^ ((o >> 3) & 0x70);
}
__device__ __forceinline__ void ldsm4(uint32_t* r, uint32_t a) {
    asm volatile("ldmatrix.sync.aligned.m8n8.x4.shared.b16 {%0,%1,%2,%3}, [%4];"
                 : "=r"(r[0]), "=r"(r[1]), "=r"(r[2]), "=r"(r[3]) : "r"(a));
}
__device__ __forceinline__ void mma16816(float* d, const uint32_t* a, const uint32_t* b) {
    asm volatile("mma.sync.aligned.m16n8k16.row.col.f32.f16.f16.f32 "
                 "{%0,%1,%2,%3}, {%4,%5,%6,%7}, {%8,%9}, {%0,%1,%2,%3};"
                 : "+f"(d[0]), "+f"(d[1]), "+f"(d[2]), "+f"(d[3])
                 : "r"(a[0]), "r"(a[1]), "r"(a[2]), "r"(a[3]), "r"(b[0]), "r"(b[1]));
}

// ---- FFMA-only transcendentals ----
__device__ __forceinline__ float exp_fast(float x) {
    x = fminf(fmaxf(x, -87.0f), 87.0f);
    float r = x * 1.4426950408889634f;
    float nf = r + 12582912.0f;
    int ni = __float_as_int(nf) - 0x4B400000;
    nf -= 12582912.0f;
    float f = fmaf(nf, -0.6931471824645996f, x);
    f = fmaf(nf, 1.9046542e-9f, f);
    float p = 1.9875691500e-4f;
    p = fmaf(p, f, 1.3981999507e-3f);
    p = fmaf(p, f, 8.3334519073e-3f);
    p = fmaf(p, f, 4.1665795894e-2f);
    p = fmaf(p, f, 1.6666665459e-1f);
    p = fmaf(p, f, 5.0000001201e-1f);
    p = fmaf(p, f, 1.0f);
    p = fmaf(p, f, 1.0f);
    return p * __int_as_float((ni + 127) << 23);
}
__device__ __forceinline__ float rcp_fast(float d) {
    float y = __int_as_float(0x7EF311C3 - __float_as_int(d));
    y = fmaf(fmaf(-d, y, 1.0f), y, y);
    y = fmaf(fmaf(-d, y, 1.0f), y, y);
    y = fmaf(fmaf(-d, y, 1.0f), y, y);
    return y;
}
__device__ __forceinline__ float sigmoid_fast(float x) { return rcp_fast(1.0f + exp_fast(-x)); }
__device__ __forceinline__ float tanh_fast(float x) {
    return fmaf(-2.0f, rcp_fast(exp_fast(2.0f * x) + 1.0f), 1.0f);
}

// ---------------- fused LSTM cell: CTA tile 64(M) x 64(N gate-cols = 16 units) ----------------
__global__ __launch_bounds__(256, 4)
void lstm_cell_mma(const __half* __restrict__ Axhi, const __half* __restrict__ Axlo,
                   const __half* __restrict__ Ahhi, const __half* __restrict__ Ahlo,
                   const __half* __restrict__ Bhi, const __half* __restrict__ Blo,
                   const float* __restrict__ biasR, float* __restrict__ C,
                   __half* __restrict__ dsthi, __half* __restrict__ dstlo,
                   float* __restrict__ Y) {
    extern __shared__ __align__(1024) char smem[];
    const uint32_t sb = smem_u32(smem);
    const int tid = threadIdx.x, wid = tid >> 5, lane = tid & 31;
    const int mw = wid & 1;        // 2 M-warps x 32 rows
    const int nw = wid >> 1;       // 4 N-warps x 16 cols
    const int m0 = blockIdx.y * 64, nt = blockIdx.x;
    const int nbase = nt * 64;

    const int a_r = mw * 32 + (lane & 7) + ((lane >> 3) & 1) * 8;
    const int a_c = ((lane >> 4) & 1) * 8;
    const int b_r = nw * 16 + (lane & 7) + ((lane >> 4) & 1) * 8;
    const int b_c = ((lane >> 3) & 1) * 8;

    float acc[2][2][4];
#pragma unroll
    for (int i = 0; i < 2; ++i)
#pragma unroll
        for (int j = 0; j < 2; ++j)
#pragma unroll
            for (int q = 0; q < 4; ++q) acc[i][j][q] = 0.0f;

    // stage loader: Ahi(64x32)|Alo|Bhi(64x32)|Blo, 1024 granules, 4/thread.
    // A granule k in [0,608): section select (x vs h) per granule (304 = 38*8).
    auto load_chunk = [&](int kc, uint32_t bs) {
        const int k0 = kc * 32;
#pragma unroll
        for (int j = 0; j < 4; ++j) {
            const int i = tid + j * 256;
            const int g = i & 255, row = g >> 2, cb = g & 3;
            if (i < 512) {
                const int part = i >> 8;               // 0=hi 1=lo
                const int k = k0 + cb * 8;
                const int sec = (k >= SEC);
                const __half* base = part ? (sec ? Ahlo : Axlo) : (sec ? Ahhi : Axhi);
                CP16(bs + part * 4096 + swzoff(row, cb * 8),
                     base + (size_t)(m0 + row) * SEC + (k - (sec ? SEC : 0)));
            } else {
                const int part = (i >> 8) & 1;         // i in [512,1024): 0=hi 1=lo
                const __half* base = part ? Blo : Bhi;
                CP16(bs + 8192 + part * 4096 + swzoff(row, cb * 8),
                     base + (size_t)(nbase + row) * KA + k0 + cb * 8);
            }
        }
        CP_COMMIT();
    };

    load_chunk(0, sb);
    load_chunk(1, sb + STAGE);

#pragma unroll 1
    for (int c = 0; c < NCH; ++c) {
        if (c + 1 < NCH) { CP_WAIT(1); } else { CP_WAIT(0); }
        __syncthreads();
        if (c + 2 < NCH) load_chunk(c + 2, sb + ((c + 2) % 3) * STAGE);

        const uint32_t bs = sb + (c % 3) * STAGE;
        const uint32_t tAhi = bs, tAlo = bs + 4096, tBhi = bs + 8192, tBlo = bs + 12288;
#pragma unroll
        for (int ks = 0; ks < 2; ++ks) {
            uint32_t Ah[2][4], Bh[4];
#pragma unroll
            for (int mi = 0; mi < 2; ++mi) ldsm4(Ah[mi], tAhi + swzoff(a_r + mi * 16, a_c + ks * 16));
            ldsm4(Bh, tBhi + swzoff(b_r, b_c + ks * 16));
#pragma unroll
            for (int mi = 0; mi < 2; ++mi)
#pragma unroll
                for (int ni = 0; ni < 2; ++ni)
                    mma16816(acc[mi][ni], Ah[mi], &Bh[ni * 2]);
            uint32_t Al[2][4];
#pragma unroll
            for (int mi = 0; mi < 2; ++mi) ldsm4(Al[mi], tAlo + swzoff(a_r + mi * 16, a_c + ks * 16));
#pragma unroll
            for (int mi = 0; mi < 2; ++mi)
#pragma unroll
                for (int ni = 0; ni < 2; ++ni)
                    mma16816(acc[mi][ni], Al[mi], &Bh[ni * 2]);
            uint32_t Bl[4];
            ldsm4(Bl, tBlo + swzoff(b_r, b_c + ks * 16));
#pragma unroll
            for (int mi = 0; mi < 2; ++mi)
#pragma unroll
                for (int ni = 0; ni < 2; ++ni)
                    mma16816(acc[mi][ni], Ah[mi], &Bl[ni * 2]);
        }
    }

    // ---- epilogue: shfl gate-exchange, LSTM update, single split-fp16 h store ----
    const int odd = lane & 1;
#pragma unroll
    for (int mi = 0; mi < 2; ++mi) {
#pragma unroll
        for (int ni = 0; ni < 2; ++ni) {
            float d0 = acc[mi][ni][0], d1 = acc[mi][ni][1], d2 = acc[mi][ni][2], d3 = acc[mi][ni][3];
            const float e0 = __shfl_xor_sync(0xFFFFFFFFu, d0, 1);
            const float e1 = __shfl_xor_sync(0xFFFFFFFFu, d1, 1);
            const float e2 = __shfl_xor_sync(0xFFFFFFFFu, d2, 1);
            const float e3 = __shfl_xor_sync(0xFFFFFFFFu, d3, 1);
            float iv, fv, gv, ov;
            int rl;
            if (!odd) { iv = d0; fv = d1; gv = e0; ov = e1; rl = lane >> 2; }
            else      { iv = e2; fv = e3; gv = d2; ov = d3; rl = (lane >> 2) + 8; }
            const int u = nt * 16 + nw * 4 + ni * 2 + ((lane >> 1) & 1);
            if (u < HDIM) {
                const int m = m0 + mw * 32 + mi * 16 + rl;
                const float4 bb = *(const float4*)(biasR + 4 * u);
                iv += bb.x; fv += bb.y; gv += bb.z; ov += bb.w;
                const float ig = sigmoid_fast(iv);
                const float fg = sigmoid_fast(fv);
                const float gg = tanh_fast(gv);
                const float og = sigmoid_fast(ov);
                const size_t ci = (size_t)m * HDIM + u;
                const float cn = fmaf(fg, C[ci], ig * gg);
                C[ci] = cn;
                const float h = og * tanh_fast(cn);
                const __half hh = __float2half_rn(h);
                const __half hl = __float2half_rn(h - __half2float(hh));
                const size_t ai = (size_t)m * SEC + u;
                dsthi[ai] = hh; dstlo[ai] = hl;
                if (Y) Y[(size_t)m * (TT * HDIM) + u] = h;
            }
        }
    }
}

// ---------------- prep kernels ----------------
__global__ void prep_weights(const float* __restrict__ Wih0, const float* __restrict__ Whh0,
                             const float* __restrict__ Wih1, const float* __restrict__ Whh1) {
    const int total = 2 * NPAD * KA;
    for (int idx = blockIdx.x * blockDim.x + threadIdx.x; idx < total; idx += gridDim.x * blockDim.x) {
        const int l = idx / (NPAD * KA), r2 = idx % (NPAD * KA);
        const int n = r2 / KA, k = r2 % KA;
        const int unit = n >> 2, gate = n & 3;
        const int kp = (k >= SEC), kk = k - (kp ? SEC : 0);
        float w = 0.f;
        if (unit < HDIM && kk < HDIM) {
            const float* W = l ? (kp ? Whh1 : Wih1) : (kp ? Whh0 : Wih0);
            w = W[(size_t)(gate * HDIM + unit) * HDIM + kk];
        }
        const __half hi = __float2half_rn(w);
        g_Bhi[l][(size_t)n * KA + k] = hi;
        g_Blo[l][(size_t)n * KA + k] = __float2half_rn(w - __half2float(hi));
    }
}

__global__ void prep_bias(const float* __restrict__ bih0, const float* __restrict__ bhh0,
                          const float* __restrict__ bih1, const float* __restrict__ bhh1) {
    for (int idx = blockIdx.x * blockDim.x + threadIdx.x; idx < 2 * NPAD; idx += gridDim.x * blockDim.x) {
        const int l = idx / NPAD, n = idx % NPAD;
        const int unit = n >> 2, gate = n & 3;
        float v = 0.f;
        if (unit < HDIM)
            v = l ? (bih1[gate * HDIM + unit] + bhh1[gate * HDIM + unit])
                  : (bih0[gate * HDIM + unit] + bhh0[gate * HDIM + unit]);
        g_biasR[l][n] = v;
    }
}

__global__ void init_state(const float* __restrict__ z) {
    const __half zh = __float2half_rn(0.f);
    const size_t total = (size_t)BQ * SEC;
    for (size_t idx = blockIdx.x * (size_t)blockDim.x + threadIdx.x; idx < total;
         idx += gridDim.x * (size_t)blockDim.x) {
        const int row = (int)(idx / SEC), col = (int)(idx % SEC);
        float v = (col < HDIM) ? z[(size_t)row * HDIM + col] : 0.f;
        const __half hi = __float2half_rn(v);
        g_Zhi[idx] = hi;
        g_Zlo[idx] = __float2half_rn(v - __half2float(hi));
        g_H0hi[0][idx] = zh; g_H0lo[0][idx] = zh;
        g_H0hi[1][idx] = zh; g_H0lo[1][idx] = zh;
        g_H1hi[0][idx] = zh; g_H1lo[0][idx] = zh;
        g_H1hi[1][idx] = zh; g_H1lo[1][idx] = zh;
        if (col < HDIM) {
            g_c[0][(size_t)row * HDIM + col] = 0.f;
            g_c[1][(size_t)row * HDIM + col] = 0.f;
        }
    }
}

// ---------------- host ----------------
extern "C" void kernel_launch(void* const* d_in, const int* in_sizes, int n_in,
                              void* d_out, int out_size) {
    const float* z    = (const float*)d_in[0];
    const float* Wih0 = (const float*)d_in[1];
    const float* Whh0 = (const float*)d_in[2];
    const float* bih0 = (const float*)d_in[3];
    const float* bhh0 = (const float*)d_in[4];
    const float* Wih1 = (const float*)d_in[5];
    const float* Whh1 = (const float*)d_in[6];
    const float* bih1 = (const float*)d_in[7];
    const float* bhh1 = (const float*)d_in[8];
    float* out = (float*)d_out;

    __half *Zhi, *Zlo, *H0hi, *H0lo, *H1hi, *H1lo, *Bhi, *Blo;
    float *biasR, *cst;
    cudaGetSymbolAddress((void**)&Zhi, g_Zhi);
    cudaGetSymbolAddress((void**)&Zlo, g_Zlo);
    cudaGetSymbolAddress((void**)&H0hi, g_H0hi);
    cudaGetSymbolAddress((void**)&H0lo, g_H0lo);
    cudaGetSymbolAddress((void**)&H1hi, g_H1hi);
    cudaGetSymbolAddress((void**)&H1lo, g_H1lo);
    cudaGetSymbolAddress((void**)&Bhi, g_Bhi);
    cudaGetSymbolAddress((void**)&Blo, g_Blo);
    cudaGetSymbolAddress((void**)&biasR, g_biasR);
    cudaGetSymbolAddress((void**)&cst, g_c);

    cudaFuncSetAttribute(lstm_cell_mma, cudaFuncAttributeMaxDynamicSharedMemorySize, SMEMB);

    prep_weights<<<2048, 256>>>(Wih0, Whh0, Wih1, Whh1);
    prep_bias<<<10, 256>>>(bih0, bhh0, bih1, bhh1);
    init_state<<<2048, 256>>>(z);

    const size_t SN = (size_t)BQ * SEC;
    const size_t BN = (size_t)NPAD * KA;
    const size_t CN = (size_t)BQ * HDIM;
    dim3 grid(19, 64);   // 19 N-tiles(64 gate-cols) x 64 M-tiles(64 rows) = 1216 CTAs
    for (int t = 0; t < TT; ++t) {
        const int p = t & 1, q = p ^ 1;
        // layer 0: x-sec = (t? h1[p] : z), h-sec = h0[p]; writes h0 -> H0[q]
        lstm_cell_mma<<<grid, 256, SMEMB>>>(
            t ? (H1hi + p * SN) : Zhi, t ? (H1lo + p * SN) : Zlo,
            H0hi + p * SN, H0lo + p * SN,
            Bhi, Blo, biasR, cst,
            H0hi + q * SN, H0lo + q * SN, nullptr);
        // layer 1: x-sec = fresh h0 = H0[q], h-sec = h1[p]; writes h1 -> H1[q]; emits Y
        lstm_cell_mma<<<grid, 256, SMEMB>>>(
            H0hi + q * SN, H0lo + q * SN,
            H1hi + p * SN, H1lo + p * SN,
            Bhi + BN, Blo + BN, biasR + NPAD, cst + CN,
            H1hi + q * SN, H1lo + q * SN, out + (size_t)t * HDIM);
    }
}